// round 7
// baseline (speedup 1.0000x reference)
#include <cuda_runtime.h>
#include <cstdint>
#include <cstddef>

// ---------------------------------------------------------------------------
// ConvPool (BPNet-style): 1x1 proj GEMM -> 7x dilated conv tower (residual,
// relu) -> profile conv (K=75) + atpm head (mean -> linear -> softplus).
// R7: dilconv A tiles stored as duplicated f32x2 pairs in smem so FFMA2
// multiplicands load directly (no pack movs). cp.async B pipeline + 2 CTAs/SM
// retained from R6. proj unchanged.
// ---------------------------------------------------------------------------

#define NPEAK 128          // B * NUM_PEAKS
#define HIDC  256
#define MOTIF_C 640
#define TS    1000         // per-row t stride
#define BUF_ELEMS (NPEAK * HIDC * TS + 4096)

typedef unsigned long long ull_t;

// dilconv smem stage, in ull (8B) units: A-dup 32k x 68 ull, B 32k x 128 ull
#define DC_AS_ULL    (32 * 68)                   // 2176 ull = 17408 B
#define DC_STAGE_ULL (DC_AS_ULL + 32 * 128)      // + 4096 ull -> 50176 B
#define DC_SMEM_BYTES (2 * DC_STAGE_ULL * 8)     // 100352 B (2 stages)

__device__ float g_bufA[BUF_ELEMS];
__device__ float g_bufB[BUF_ELEMS];

__device__ __forceinline__ float softplusf(float x) {
    return fmaxf(x, 0.0f) + log1pf(expf(-fabsf(x)));
}

__device__ __forceinline__ ull_t pack2(float x, float y) {
    ull_t r;
    asm("mov.b64 %0, {%1, %2};" : "=l"(r) : "f"(x), "f"(y));
    return r;
}
__device__ __forceinline__ float2 unpack2(ull_t v) {
    float2 r;
    asm("mov.b64 {%0, %1}, %2;" : "=f"(r.x), "=f"(r.y) : "l"(v));
    return r;
}
__device__ __forceinline__ void ffma2(ull_t& d, ull_t a, ull_t b) {
    asm("fma.rn.f32x2 %0, %1, %2, %0;" : "+l"(d) : "l"(a), "l"(b));
}

// ---- micro-kernel with PACKED A (pre-duplicated pairs in smem) -------------
// As2: [k][c] as ull, stride 68 (warp-uniform broadcast reads)
// Bs:  [k][t] floats, stride 256
__device__ __forceinline__ void compute32_dup(
    const ull_t* __restrict__ As2, const float* __restrict__ Bs,
    int tx, int ty, ull_t acc[8][4])
{
#pragma unroll
    for (int kk = 0; kk < 32; kk++) {
        const ull_t* ap = As2 + kk * 68 + ty * 4;
        ulonglong2 a01 = *(const ulonglong2*)(ap);
        ulonglong2 a23 = *(const ulonglong2*)(ap + 2);
        ulonglong2 a45 = *(const ulonglong2*)(ap + 32);
        ulonglong2 a67 = *(const ulonglong2*)(ap + 34);
        ull_t av[8] = {a01.x, a01.y, a23.x, a23.y,
                       a45.x, a45.y, a67.x, a67.y};
        ulonglong2 b0 = *(const ulonglong2*)(Bs + kk * 256 + tx * 4);
        ulonglong2 b1 = *(const ulonglong2*)(Bs + kk * 256 + 128 + tx * 4);
        ull_t bv[4] = {b0.x, b0.y, b1.x, b1.y};
#pragma unroll
        for (int i = 0; i < 8; i++)
#pragma unroll
            for (int j = 0; j < 4; j++)
                ffma2(acc[i][j], av[i], bv[j]);
    }
}

// ---- micro-kernel with scalar A + in-register pack (proj) ------------------
__device__ __forceinline__ void compute32_pack(
    const float* __restrict__ As, const float* __restrict__ Bs,
    int tx, int ty, ull_t acc[8][4])
{
#pragma unroll
    for (int kk = 0; kk < 32; kk++) {
        float4 a0 = *(const float4*)(As + kk * 68 + ty * 4);
        float4 a1 = *(const float4*)(As + kk * 68 + 32 + ty * 4);
        ull_t av[8];
        av[0] = pack2(a0.x, a0.x); av[1] = pack2(a0.y, a0.y);
        av[2] = pack2(a0.z, a0.z); av[3] = pack2(a0.w, a0.w);
        av[4] = pack2(a1.x, a1.x); av[5] = pack2(a1.y, a1.y);
        av[6] = pack2(a1.z, a1.z); av[7] = pack2(a1.w, a1.w);
        ulonglong2 b0 = *(const ulonglong2*)(Bs + kk * 256 + tx * 4);
        ulonglong2 b1 = *(const ulonglong2*)(Bs + kk * 256 + 128 + tx * 4);
        ull_t bv[4] = {b0.x, b0.y, b1.x, b1.y};
#pragma unroll
        for (int i = 0; i < 8; i++)
#pragma unroll
            for (int j = 0; j < 4; j++)
                ffma2(acc[i][j], av[i], bv[j]);
    }
}

// ---------------------------------------------------------------------------
// Projection GEMM (unchanged from R6/R4)
// ---------------------------------------------------------------------------
__device__ __forceinline__ void pj_loadA(const float* __restrict__ w, int c0,
                                         int tid, int k0, float pA[8])
{
#pragma unroll
    for (int i = 0; i < 8; i++) {
        int idx = tid + i * 256;
        int kk = idx & 31, cc = idx >> 5;
        pA[i] = w[(size_t)(c0 + cc) * MOTIF_C + k0 + kk];
    }
}
__device__ __forceinline__ void pj_loadB(const float* __restrict__ x, int pos0,
                                         int tid, int k0, float4 pB[8])
{
#pragma unroll
    for (int i = 0; i < 8; i++) {
        int idx = tid + i * 256;
        int f4 = idx & 7, pl = idx >> 3;
        pB[i] = *(const float4*)(x + (size_t)(pos0 + pl) * MOTIF_C + k0 + f4 * 4);
    }
}

__global__ __launch_bounds__(256) void proj_kernel(
    const float* __restrict__ x, const float* __restrict__ w,
    const float* __restrict__ bias, float* __restrict__ out)
{
    __shared__ float As[32][68];
    __shared__ float Bs[32][256];
    const int tid = threadIdx.x;
    const int tx = tid & 31, ty = tid >> 5;
    const int pos0 = blockIdx.x * 256;
    const int c0 = blockIdx.y * 64;

    ull_t acc[8][4];
#pragma unroll
    for (int i = 0; i < 8; i++)
#pragma unroll
        for (int j = 0; j < 4; j++) acc[i][j] = 0ull;

    float pA[8];
    float4 pB[8];
    pj_loadA(w, c0, tid, 0, pA);
    pj_loadB(x, pos0, tid, 0, pB);

#pragma unroll 1
    for (int k0 = 0; k0 < MOTIF_C; k0 += 32) {
        __syncthreads();
#pragma unroll
        for (int i = 0; i < 8; i++) {
            int idx = tid + i * 256;
            As[idx & 31][idx >> 5] = pA[i];
        }
#pragma unroll
        for (int i = 0; i < 8; i++) {
            int idx = tid + i * 256;
            int f4 = idx & 7, pl = idx >> 3;
            Bs[f4 * 4 + 0][pl] = pB[i].x;
            Bs[f4 * 4 + 1][pl] = pB[i].y;
            Bs[f4 * 4 + 2][pl] = pB[i].z;
            Bs[f4 * 4 + 3][pl] = pB[i].w;
        }
        __syncthreads();
        if (k0 + 32 < MOTIF_C) {
            pj_loadA(w, c0, tid, k0 + 32, pA);
            pj_loadB(x, pos0, tid, k0 + 32, pB);
        }
        compute32_pack(&As[0][0], &Bs[0][0], tx, ty, acc);
    }

#pragma unroll
    for (int ii = 0; ii < 8; ii++) {
        int c = c0 + ((ii < 4) ? (ty * 4 + ii) : (32 + ty * 4 + ii - 4));
        float bvv = bias[c];
#pragma unroll
        for (int g = 0; g < 2; g++) {
            float2 u0 = unpack2(acc[ii][g * 2 + 0]);
            float2 u1 = unpack2(acc[ii][g * 2 + 1]);
            float v[4] = {u0.x, u0.y, u1.x, u1.y};
#pragma unroll
            for (int e = 0; e < 4; e++) {
                int pos = pos0 + g * 128 + tx * 4 + e;
                int pb = pos / 1000;
                int tb = pos - pb * 1000;
                out[(size_t)pb * (HIDC * TS) + (size_t)c * TS + tb] = v[e] + bvv;
            }
        }
    }
}

// ---------------------------------------------------------------------------
// Dilated conv: cp.async B pipeline, A-dup smem, 2-stage, 2 CTAs/SM.
// ---------------------------------------------------------------------------
__device__ __forceinline__ void dc_loadA(const float* __restrict__ w, int c0,
                                         int tid, int chunk, float pA[8])
{
    int k = chunk >> 3, ci0 = (chunk & 7) << 5;
#pragma unroll
    for (int i = 0; i < 8; i++) {
        int idx = tid + i * 256;
        int ci = idx & 31, cc = idx >> 5;
        pA[i] = w[(size_t)(c0 + cc) * 768 + (ci0 + ci) * 3 + k];
    }
}

// issue 32KB B tile via cp.async (2 x 8B per thread per i; toff even -> 8B ok)
__device__ __forceinline__ void dc_issueB(const float* __restrict__ hp, int t0,
                                          int dil, int tid, int chunk,
                                          float* Bsw)
{
    int k = chunk >> 3, ci0 = (chunk & 7) << 5;
    int toff = t0 + k * dil;
    unsigned bbase = (unsigned)__cvta_generic_to_shared(Bsw);
#pragma unroll
    for (int i = 0; i < 8; i++) {
        int idx = tid + i * 256;
        int f4 = idx & 63, ci = idx >> 6;
        const float* src = hp + (size_t)(ci0 + ci) * TS + toff + f4 * 4;
        unsigned dst = bbase + (unsigned)(ci * 256 + f4 * 4) * 4u;
        asm volatile("cp.async.ca.shared.global [%0], [%1], 8;"
                     :: "r"(dst), "l"(src) : "memory");
        asm volatile("cp.async.ca.shared.global [%0], [%1], 8;"
                     :: "r"(dst + 8), "l"(src + 2) : "memory");
    }
    asm volatile("cp.async.commit_group;" ::: "memory");
}

__global__ __launch_bounds__(256, 2) void dilconv_kernel(
    const float* __restrict__ hin, const float* __restrict__ w,
    const float* __restrict__ bias, float* __restrict__ hout,
    int dil, int len_out)
{
    extern __shared__ ull_t smu[];
    const int tid = threadIdx.x;
    const int tx = tid & 31, ty = tid >> 5;
    const int t0 = blockIdx.x * 256;
    const int c0 = blockIdx.y * 64;
    const int p  = blockIdx.z;
    const float* __restrict__ hp = hin + (size_t)p * (HIDC * TS);

    ull_t acc[8][4];
#pragma unroll
    for (int i = 0; i < 8; i++)
#pragma unroll
        for (int j = 0; j < 4; j++) acc[i][j] = 0ull;

    float pA[8];
    dc_loadA(w, c0, tid, 0, pA);
    dc_issueB(hp, t0, dil, tid, 0, (float*)(smu + DC_AS_ULL)); // B(0)->stage 0

#pragma unroll 1
    for (int ch = 0; ch < 24; ch++) {
        ull_t* Asw = smu + (ch & 1) * DC_STAGE_ULL;
        float* Bsw = (float*)(Asw + DC_AS_ULL);
        // store A(ch) as duplicated pairs. Safe: all warps passed sync(ch-1),
        // i.e. finished compute(ch-2), the last reader of this stage.
#pragma unroll
        for (int i = 0; i < 8; i++) {
            int idx = tid + i * 256;
            Asw[(idx & 31) * 68 + (idx >> 5)] = pack2(pA[i], pA[i]);
        }
        asm volatile("cp.async.wait_group 0;" ::: "memory");  // B(ch) landed
        __syncthreads();
        if (ch + 1 < 24) {
            dc_issueB(hp, t0, dil, tid, ch + 1,
                      (float*)(smu + ((ch + 1) & 1) * DC_STAGE_ULL + DC_AS_ULL));
            dc_loadA(w, c0, tid, ch + 1, pA);
        }
        compute32_dup(Asw, Bsw, tx, ty, acc);
    }

    float* __restrict__ op = hout + (size_t)p * (HIDC * TS);
#pragma unroll
    for (int ii = 0; ii < 8; ii++) {
        int c = c0 + ((ii < 4) ? (ty * 4 + ii) : (32 + ty * 4 + ii - 4));
        float bvv = bias[c];
        const float* rp = hp + (size_t)c * TS + dil;
        float* o = op + (size_t)c * TS;
#pragma unroll
        for (int g = 0; g < 2; g++) {
            int t = t0 + g * 128 + tx * 4;
            float2 u0 = unpack2(acc[ii][g * 2 + 0]);
            float2 u1 = unpack2(acc[ii][g * 2 + 1]);
            float v[4] = {u0.x, u0.y, u1.x, u1.y};
#pragma unroll
            for (int e = 0; e < 4; e++) {
                if (t + e < len_out)
                    o[t + e] = fmaxf(v[e] + bvv, 0.f) + rp[t + e];
            }
        }
    }
}

// ---------------------------------------------------------------------------
// Profile head: out[p][t] = softplus(sum_{c,j} h[p][c][t+j] * wp[c][j] + bp)
// ---------------------------------------------------------------------------
__global__ __launch_bounds__(256) void profile_kernel(
    const float* __restrict__ h, const float* __restrict__ wp,
    const float* __restrict__ bp, float* __restrict__ out)
{
    __shared__ float ws[64 * 75];
    __shared__ float red[256];
    const int tid = threadIdx.x;
    const int tt = tid & 63, g = tid >> 6;
    const int p = blockIdx.y;
    const int t = blockIdx.x * 64 + tt;
    const float* __restrict__ hp = h + (size_t)p * (HIDC * TS);

    float acc = 0.f;
#pragma unroll 1
    for (int cb = 0; cb < HIDC; cb += 64) {
        __syncthreads();
        for (int idx = tid; idx < 64 * 75; idx += 256) ws[idx] = wp[cb * 75 + idx];
        __syncthreads();
#pragma unroll 1
        for (int cc = 0; cc < 16; cc++) {
            int c = cb + g * 16 + cc;
            const float* hr = hp + (size_t)c * TS + t;
            const float* wr = ws + (g * 16 + cc) * 75;
            float s = 0.f;
#pragma unroll
            for (int j = 0; j < 75; j++) s = fmaf(hr[j], wr[j], s);
            acc += s;
        }
    }
    red[tid] = acc;
    __syncthreads();
    if (g == 0 && t < 418) {
        float tot = red[tt] + red[tt + 64] + red[tt + 128] + red[tt + 192] + bp[0];
        out[128 + p * 418 + t] = softplusf(tot);
    }
}

// ---------------------------------------------------------------------------
// ATPM head
// ---------------------------------------------------------------------------
__global__ __launch_bounds__(256) void atpm_kernel(
    const float* __restrict__ h, const float* __restrict__ wa,
    const float* __restrict__ ba, float* __restrict__ out)
{
    __shared__ float red[256];
    const int tid = threadIdx.x;
    const int p = blockIdx.x;
    const float* __restrict__ hr = h + (size_t)p * (HIDC * TS) + (size_t)tid * TS;
    float s = 0.f;
#pragma unroll 1
    for (int t4 = 0; t4 < 492; t4 += 4) {
        float4 v = *(const float4*)(hr + t4);
        s += (v.x + v.y) + (v.z + v.w);
    }
    red[tid] = (s * (1.0f / 492.0f)) * wa[tid];
    __syncthreads();
    for (int off = 128; off > 0; off >>= 1) {
        if (tid < off) red[tid] += red[tid + off];
        __syncthreads();
    }
    if (tid == 0) out[p] = softplusf(red[0] + ba[0]);
}

// ---------------------------------------------------------------------------
extern "C" void kernel_launch(void* const* d_in, const int* in_sizes, int n_in,
                              void* d_out, int out_size)
{
    (void)out_size;
    int pbase = 4;
    if (n_in == 11) pbase = 3;
    else if (n_in == 12 && in_sizes[3] != 1) pbase = 3;

    const float* x      = (const float*)d_in[0];
    const float* w_proj = (const float*)d_in[pbase + 0];
    const float* b_proj = (const float*)d_in[pbase + 1];
    const float* w_dil  = (const float*)d_in[pbase + 2];
    const float* b_dil  = (const float*)d_in[pbase + 3];
    const float* w_prof = (const float*)d_in[pbase + 4];
    const float* b_prof = (const float*)d_in[pbase + 5];
    const float* w_atpm = (const float*)d_in[pbase + 6];
    const float* b_atpm = (const float*)d_in[pbase + 7];
    float* out = (float*)d_out;

    float *bufA, *bufB;
    cudaGetSymbolAddress((void**)&bufA, g_bufA);
    cudaGetSymbolAddress((void**)&bufB, g_bufB);

    cudaFuncSetAttribute(dilconv_kernel,
                         cudaFuncAttributeMaxDynamicSharedMemorySize,
                         DC_SMEM_BYTES);

    // 1x1 projection GEMM: 128000 pos x 256 ch, K=640
    proj_kernel<<<dim3(500, 4), 256>>>(x, w_proj, b_proj, bufA);

    // dilated conv tower, ping-pong buffers
    static const int lens[8] = {1000, 996, 988, 972, 940, 876, 748, 492};
    float* cur = bufA;
    float* nxt = bufB;
    for (int l = 0; l < 7; l++) {
        int dil = 2 << l;
        int lo = lens[l + 1];
        dim3 grid((lo + 255) / 256, 4, NPEAK);
        dilconv_kernel<<<grid, 256, DC_SMEM_BYTES>>>(
            cur, w_dil + (size_t)l * 196608, b_dil + l * 256, nxt, dil, lo);
        float* tmp = cur; cur = nxt; nxt = tmp;
    }

    // heads (final activations live in `cur`, len 492)
    atpm_kernel<<<NPEAK, 256>>>(cur, w_atpm, b_atpm, out);
    profile_kernel<<<dim3(7, NPEAK), 256>>>(cur, w_prof, b_prof, out);
}

// round 8
// speedup vs baseline: 1.2624x; 1.2624x over previous
#include <cuda_runtime.h>
#include <cstdint>
#include <cstddef>

// ---------------------------------------------------------------------------
// ConvPool (BPNet-style): 1x1 proj GEMM -> 7x dilated conv tower (residual,
// relu) -> profile conv (K=75) + atpm head (mean -> linear -> softplus).
// R8: revert dilconv to proven R6 structure (pack-mov FFMA2 micro-kernel,
// cp.async 2-stage, 2 CTAs/SM) + 16B cp.async fast path when aligned.
// ---------------------------------------------------------------------------

#define NPEAK 128          // B * NUM_PEAKS
#define HIDC  256
#define MOTIF_C 640
#define TS    1000         // per-row t stride
#define BUF_ELEMS (NPEAK * HIDC * TS + 4096)

#define AS_FLOATS (32 * 68)
#define STAGE_FLOATS (AS_FLOATS + 32 * 256)   // 10368 floats = 41472 B
#define DC_SMEM_BYTES (2 * STAGE_FLOATS * 4)  // 82944 B (2 stages)

typedef unsigned long long ull_t;

__device__ float g_bufA[BUF_ELEMS];
__device__ float g_bufB[BUF_ELEMS];

__device__ __forceinline__ float softplusf(float x) {
    return fmaxf(x, 0.0f) + log1pf(expf(-fabsf(x)));
}

__device__ __forceinline__ ull_t pack2(float x, float y) {
    ull_t r;
    asm("mov.b64 %0, {%1, %2};" : "=l"(r) : "f"(x), "f"(y));
    return r;
}
__device__ __forceinline__ float2 unpack2(ull_t v) {
    float2 r;
    asm("mov.b64 {%0, %1}, %2;" : "=f"(r.x), "=f"(r.y) : "l"(v));
    return r;
}
__device__ __forceinline__ void ffma2(ull_t& d, ull_t a, ull_t b) {
    asm("fma.rn.f32x2 %0, %1, %2, %0;" : "+l"(d) : "l"(a), "l"(b));
}

// 8x8 micro-kernel (8 ch x 4 f32x2 pairs) over a 32-deep K tile.
// As: [k][c] stride 68 (warp-uniform broadcast reads); Bs: [k][t] stride 256.
// pack movs go to the idle ALU pipe (R7 lesson: do NOT move them to LDS).
__device__ __forceinline__ void compute32(
    const float* __restrict__ As, const float* __restrict__ Bs,
    int tx, int ty, ull_t acc[8][4])
{
#pragma unroll
    for (int kk = 0; kk < 32; kk++) {
        float4 a0 = *(const float4*)(As + kk * 68 + ty * 4);
        float4 a1 = *(const float4*)(As + kk * 68 + 32 + ty * 4);
        ull_t av[8];
        av[0] = pack2(a0.x, a0.x); av[1] = pack2(a0.y, a0.y);
        av[2] = pack2(a0.z, a0.z); av[3] = pack2(a0.w, a0.w);
        av[4] = pack2(a1.x, a1.x); av[5] = pack2(a1.y, a1.y);
        av[6] = pack2(a1.z, a1.z); av[7] = pack2(a1.w, a1.w);
        ulonglong2 b0 = *(const ulonglong2*)(Bs + kk * 256 + tx * 4);
        ulonglong2 b1 = *(const ulonglong2*)(Bs + kk * 256 + 128 + tx * 4);
        ull_t bv[4] = {b0.x, b0.y, b1.x, b1.y};
#pragma unroll
        for (int i = 0; i < 8; i++)
#pragma unroll
            for (int j = 0; j < 4; j++)
                ffma2(acc[i][j], av[i], bv[j]);
    }
}

// ---------------------------------------------------------------------------
// Projection GEMM (unchanged: R4/R6 structure)
// ---------------------------------------------------------------------------
__device__ __forceinline__ void pj_loadA(const float* __restrict__ w, int c0,
                                         int tid, int k0, float pA[8])
{
#pragma unroll
    for (int i = 0; i < 8; i++) {
        int idx = tid + i * 256;
        int kk = idx & 31, cc = idx >> 5;
        pA[i] = w[(size_t)(c0 + cc) * MOTIF_C + k0 + kk];
    }
}
__device__ __forceinline__ void pj_loadB(const float* __restrict__ x, int pos0,
                                         int tid, int k0, float4 pB[8])
{
#pragma unroll
    for (int i = 0; i < 8; i++) {
        int idx = tid + i * 256;
        int f4 = idx & 7, pl = idx >> 3;
        pB[i] = *(const float4*)(x + (size_t)(pos0 + pl) * MOTIF_C + k0 + f4 * 4);
    }
}

__global__ __launch_bounds__(256) void proj_kernel(
    const float* __restrict__ x, const float* __restrict__ w,
    const float* __restrict__ bias, float* __restrict__ out)
{
    __shared__ float As[32][68];
    __shared__ float Bs[32][256];
    const int tid = threadIdx.x;
    const int tx = tid & 31, ty = tid >> 5;
    const int pos0 = blockIdx.x * 256;
    const int c0 = blockIdx.y * 64;

    ull_t acc[8][4];
#pragma unroll
    for (int i = 0; i < 8; i++)
#pragma unroll
        for (int j = 0; j < 4; j++) acc[i][j] = 0ull;

    float pA[8];
    float4 pB[8];
    pj_loadA(w, c0, tid, 0, pA);
    pj_loadB(x, pos0, tid, 0, pB);

#pragma unroll 1
    for (int k0 = 0; k0 < MOTIF_C; k0 += 32) {
        __syncthreads();
#pragma unroll
        for (int i = 0; i < 8; i++) {
            int idx = tid + i * 256;
            As[idx & 31][idx >> 5] = pA[i];
        }
#pragma unroll
        for (int i = 0; i < 8; i++) {
            int idx = tid + i * 256;
            int f4 = idx & 7, pl = idx >> 3;
            Bs[f4 * 4 + 0][pl] = pB[i].x;
            Bs[f4 * 4 + 1][pl] = pB[i].y;
            Bs[f4 * 4 + 2][pl] = pB[i].z;
            Bs[f4 * 4 + 3][pl] = pB[i].w;
        }
        __syncthreads();
        if (k0 + 32 < MOTIF_C) {
            pj_loadA(w, c0, tid, k0 + 32, pA);
            pj_loadB(x, pos0, tid, k0 + 32, pB);
        }
        compute32(&As[0][0], &Bs[0][0], tx, ty, acc);
    }

#pragma unroll
    for (int ii = 0; ii < 8; ii++) {
        int c = c0 + ((ii < 4) ? (ty * 4 + ii) : (32 + ty * 4 + ii - 4));
        float bvv = bias[c];
#pragma unroll
        for (int g = 0; g < 2; g++) {
            float2 u0 = unpack2(acc[ii][g * 2 + 0]);
            float2 u1 = unpack2(acc[ii][g * 2 + 1]);
            float v[4] = {u0.x, u0.y, u1.x, u1.y};
#pragma unroll
            for (int e = 0; e < 4; e++) {
                int pos = pos0 + g * 128 + tx * 4 + e;
                int pb = pos / 1000;
                int tb = pos - pb * 1000;
                out[(size_t)pb * (HIDC * TS) + (size_t)c * TS + tb] = v[e] + bvv;
            }
        }
    }
}

// ---------------------------------------------------------------------------
// Dilated conv: cp.async B pipeline, 2-stage, 2 CTAs/SM. (R6 structure)
// ---------------------------------------------------------------------------
__device__ __forceinline__ void dc_loadA(const float* __restrict__ w, int c0,
                                         int tid, int chunk, float pA[8])
{
    int k = chunk >> 3, ci0 = (chunk & 7) << 5;
#pragma unroll
    for (int i = 0; i < 8; i++) {
        int idx = tid + i * 256;
        int ci = idx & 31, cc = idx >> 5;
        pA[i] = w[(size_t)(c0 + cc) * 768 + (ci0 + ci) * 3 + k];
    }
}

// issue 32KB B tile via cp.async; 16B ops when the tap offset is 16B-aligned
// (all chunks of dil>=4; taps 0,2 of dil=2), else 2 x 8B (toff always even).
__device__ __forceinline__ void dc_issueB(const float* __restrict__ hp, int t0,
                                          int dil, int tid, int chunk,
                                          float* Bsw)
{
    int k = chunk >> 3, ci0 = (chunk & 7) << 5;
    int toff = t0 + k * dil;
    unsigned bbase = (unsigned)__cvta_generic_to_shared(Bsw);
    if ((toff & 3) == 0) {
#pragma unroll
        for (int i = 0; i < 8; i++) {
            int idx = tid + i * 256;
            int f4 = idx & 63, ci = idx >> 6;
            const float* src = hp + (size_t)(ci0 + ci) * TS + toff + f4 * 4;
            unsigned dst = bbase + (unsigned)(ci * 256 + f4 * 4) * 4u;
            asm volatile("cp.async.ca.shared.global [%0], [%1], 16;"
                         :: "r"(dst), "l"(src) : "memory");
        }
    } else {
#pragma unroll
        for (int i = 0; i < 8; i++) {
            int idx = tid + i * 256;
            int f4 = idx & 63, ci = idx >> 6;
            const float* src = hp + (size_t)(ci0 + ci) * TS + toff + f4 * 4;
            unsigned dst = bbase + (unsigned)(ci * 256 + f4 * 4) * 4u;
            asm volatile("cp.async.ca.shared.global [%0], [%1], 8;"
                         :: "r"(dst), "l"(src) : "memory");
            asm volatile("cp.async.ca.shared.global [%0], [%1], 8;"
                         :: "r"(dst + 8), "l"(src + 2) : "memory");
        }
    }
    asm volatile("cp.async.commit_group;" ::: "memory");
}

__global__ __launch_bounds__(256, 2) void dilconv_kernel(
    const float* __restrict__ hin, const float* __restrict__ w,
    const float* __restrict__ bias, float* __restrict__ hout,
    int dil, int len_out)
{
    extern __shared__ float sm[];
    const int tid = threadIdx.x;
    const int tx = tid & 31, ty = tid >> 5;
    const int t0 = blockIdx.x * 256;
    const int c0 = blockIdx.y * 64;
    const int p  = blockIdx.z;
    const float* __restrict__ hp = hin + (size_t)p * (HIDC * TS);

    ull_t acc[8][4];
#pragma unroll
    for (int i = 0; i < 8; i++)
#pragma unroll
        for (int j = 0; j < 4; j++) acc[i][j] = 0ull;

    float pA[8];
    dc_loadA(w, c0, tid, 0, pA);
    dc_issueB(hp, t0, dil, tid, 0, sm + AS_FLOATS);   // B(0) -> stage 0

#pragma unroll 1
    for (int ch = 0; ch < 24; ch++) {
        float* Asw = sm + (ch & 1) * STAGE_FLOATS;
        float* Bsw = Asw + AS_FLOATS;
        // store A(ch). Safe: all warps passed sync(ch-1), i.e. finished
        // compute(ch-2), the last reader of this stage's A.
#pragma unroll
        for (int i = 0; i < 8; i++) {
            int idx = tid + i * 256;
            Asw[(idx & 31) * 68 + (idx >> 5)] = pA[i];
        }
        asm volatile("cp.async.wait_group 0;" ::: "memory");  // B(ch) landed
        __syncthreads();
        if (ch + 1 < 24) {
            // B(ch+1) -> stage (ch+1)&1: all warps finished compute(ch-1),
            // the last reader of that stage, because they passed sync(ch).
            dc_issueB(hp, t0, dil, tid, ch + 1,
                      sm + ((ch + 1) & 1) * STAGE_FLOATS + AS_FLOATS);
            dc_loadA(w, c0, tid, ch + 1, pA);
        }
        compute32(Asw, Bsw, tx, ty, acc);
    }

    float* __restrict__ op = hout + (size_t)p * (HIDC * TS);
#pragma unroll
    for (int ii = 0; ii < 8; ii++) {
        int c = c0 + ((ii < 4) ? (ty * 4 + ii) : (32 + ty * 4 + ii - 4));
        float bvv = bias[c];
        const float* rp = hp + (size_t)c * TS + dil;
        float* o = op + (size_t)c * TS;
#pragma unroll
        for (int g = 0; g < 2; g++) {
            int t = t0 + g * 128 + tx * 4;
            float2 u0 = unpack2(acc[ii][g * 2 + 0]);
            float2 u1 = unpack2(acc[ii][g * 2 + 1]);
            float v[4] = {u0.x, u0.y, u1.x, u1.y};
#pragma unroll
            for (int e = 0; e < 4; e++) {
                if (t + e < len_out)
                    o[t + e] = fmaxf(v[e] + bvv, 0.f) + rp[t + e];
            }
        }
    }
}

// ---------------------------------------------------------------------------
// Profile head: out[p][t] = softplus(sum_{c,j} h[p][c][t+j] * wp[c][j] + bp)
// ---------------------------------------------------------------------------
__global__ __launch_bounds__(256) void profile_kernel(
    const float* __restrict__ h, const float* __restrict__ wp,
    const float* __restrict__ bp, float* __restrict__ out)
{
    __shared__ float ws[64 * 75];
    __shared__ float red[256];
    const int tid = threadIdx.x;
    const int tt = tid & 63, g = tid >> 6;
    const int p = blockIdx.y;
    const int t = blockIdx.x * 64 + tt;
    const float* __restrict__ hp = h + (size_t)p * (HIDC * TS);

    float acc = 0.f;
#pragma unroll 1
    for (int cb = 0; cb < HIDC; cb += 64) {
        __syncthreads();
        for (int idx = tid; idx < 64 * 75; idx += 256) ws[idx] = wp[cb * 75 + idx];
        __syncthreads();
#pragma unroll 1
        for (int cc = 0; cc < 16; cc++) {
            int c = cb + g * 16 + cc;
            const float* hr = hp + (size_t)c * TS + t;
            const float* wr = ws + (g * 16 + cc) * 75;
            float s = 0.f;
#pragma unroll
            for (int j = 0; j < 75; j++) s = fmaf(hr[j], wr[j], s);
            acc += s;
        }
    }
    red[tid] = acc;
    __syncthreads();
    if (g == 0 && t < 418) {
        float tot = red[tt] + red[tt + 64] + red[tt + 128] + red[tt + 192] + bp[0];
        out[128 + p * 418 + t] = softplusf(tot);
    }
}

// ---------------------------------------------------------------------------
// ATPM head
// ---------------------------------------------------------------------------
__global__ __launch_bounds__(256) void atpm_kernel(
    const float* __restrict__ h, const float* __restrict__ wa,
    const float* __restrict__ ba, float* __restrict__ out)
{
    __shared__ float red[256];
    const int tid = threadIdx.x;
    const int p = blockIdx.x;
    const float* __restrict__ hr = h + (size_t)p * (HIDC * TS) + (size_t)tid * TS;
    float s = 0.f;
#pragma unroll 1
    for (int t4 = 0; t4 < 492; t4 += 4) {
        float4 v = *(const float4*)(hr + t4);
        s += (v.x + v.y) + (v.z + v.w);
    }
    red[tid] = (s * (1.0f / 492.0f)) * wa[tid];
    __syncthreads();
    for (int off = 128; off > 0; off >>= 1) {
        if (tid < off) red[tid] += red[tid + off];
        __syncthreads();
    }
    if (tid == 0) out[p] = softplusf(red[0] + ba[0]);
}

// ---------------------------------------------------------------------------
extern "C" void kernel_launch(void* const* d_in, const int* in_sizes, int n_in,
                              void* d_out, int out_size)
{
    (void)out_size;
    int pbase = 4;
    if (n_in == 11) pbase = 3;
    else if (n_in == 12 && in_sizes[3] != 1) pbase = 3;

    const float* x      = (const float*)d_in[0];
    const float* w_proj = (const float*)d_in[pbase + 0];
    const float* b_proj = (const float*)d_in[pbase + 1];
    const float* w_dil  = (const float*)d_in[pbase + 2];
    const float* b_dil  = (const float*)d_in[pbase + 3];
    const float* w_prof = (const float*)d_in[pbase + 4];
    const float* b_prof = (const float*)d_in[pbase + 5];
    const float* w_atpm = (const float*)d_in[pbase + 6];
    const float* b_atpm = (const float*)d_in[pbase + 7];
    float* out = (float*)d_out;

    float *bufA, *bufB;
    cudaGetSymbolAddress((void**)&bufA, g_bufA);
    cudaGetSymbolAddress((void**)&bufB, g_bufB);

    cudaFuncSetAttribute(dilconv_kernel,
                         cudaFuncAttributeMaxDynamicSharedMemorySize,
                         DC_SMEM_BYTES);

    // 1x1 projection GEMM: 128000 pos x 256 ch, K=640
    proj_kernel<<<dim3(500, 4), 256>>>(x, w_proj, b_proj, bufA);

    // dilated conv tower, ping-pong buffers
    static const int lens[8] = {1000, 996, 988, 972, 940, 876, 748, 492};
    float* cur = bufA;
    float* nxt = bufB;
    for (int l = 0; l < 7; l++) {
        int dil = 2 << l;
        int lo = lens[l + 1];
        dim3 grid((lo + 255) / 256, 4, NPEAK);
        dilconv_kernel<<<grid, 256, DC_SMEM_BYTES>>>(
            cur, w_dil + (size_t)l * 196608, b_dil + l * 256, nxt, dil, lo);
        float* tmp = cur; cur = nxt; nxt = tmp;
    }

    // heads (final activations live in `cur`, len 492)
    atpm_kernel<<<NPEAK, 256>>>(cur, w_atpm, b_atpm, out);
    profile_kernel<<<dim3(7, NPEAK), 256>>>(cur, w_prof, b_prof, out);
}

// round 12
// speedup vs baseline: 1.3868x; 1.0985x over previous
#include <cuda_runtime.h>
#include <cuda_bf16.h>
#include <cstdint>
#include <cstddef>

// ---------------------------------------------------------------------------
// ConvPool: 1x1 proj GEMM (FFMA2) -> 7x dilated conv tower on mma.sync HMMA
// (3-term bf16 split: AhiBhi + AhiBlo + AloBhi, fp32 accum) -> heads.
// tcgen05 is unavailable (harness targets sm_103 without 'a'); mma.sync is
// baseline PTX. Activations [p][t][c] as bf16 (hi, lo) pairs. R12.
// ---------------------------------------------------------------------------

#define NPEAK 128
#define HIDC  256
#define MOTIF_C 640
#define POFF  (1000 * 256)                 // per-peak elems in [t][c] layout
#define HBUF  (NPEAK * POFF + 131072)      // + pad for B-tile overreads
#define WBUF  (7 * 256 * 768)

typedef unsigned long long ull_t;
typedef __nv_bfloat16 bf16;

__device__ bf16 g_hiA[HBUF];
__device__ bf16 g_loA[HBUF];
__device__ bf16 g_hiB[HBUF];
__device__ bf16 g_loB[HBUF];
__device__ bf16 g_whi[WBUF];
__device__ bf16 g_wlo[WBUF];

// ---- helpers --------------------------------------------------------------
__device__ __forceinline__ float softplusf(float x) {
    return fmaxf(x, 0.0f) + log1pf(expf(-fabsf(x)));
}
__device__ __forceinline__ ull_t pack2(float x, float y) {
    ull_t r; asm("mov.b64 %0, {%1, %2};" : "=l"(r) : "f"(x), "f"(y)); return r;
}
__device__ __forceinline__ float2 unpack2(ull_t v) {
    float2 r; asm("mov.b64 {%0, %1}, %2;" : "=f"(r.x), "=f"(r.y) : "l"(v)); return r;
}
__device__ __forceinline__ void ffma2(ull_t& d, ull_t a, ull_t b) {
    asm("fma.rn.f32x2 %0, %1, %2, %0;" : "+l"(d) : "l"(a), "l"(b));
}
__device__ __forceinline__ unsigned smem_u32(const void* p) {
    unsigned r;
    asm("{ .reg .u64 t; cvta.to.shared.u64 t, %1; cvt.u32.u64 %0, t; }"
        : "=r"(r) : "l"(p));
    return r;
}
#define CP16(dst, src) \
    asm volatile("cp.async.ca.shared.global [%0], [%1], 16;" \
                 :: "r"(dst), "l"(src) : "memory")

__device__ __forceinline__ void mma16816(float c[4], const unsigned a[4],
                                         const unsigned b[2]) {
    asm volatile(
        "mma.sync.aligned.m16n8k16.row.col.f32.bf16.bf16.f32 "
        "{%0,%1,%2,%3}, {%4,%5,%6,%7}, {%8,%9}, {%0,%1,%2,%3};"
        : "+f"(c[0]), "+f"(c[1]), "+f"(c[2]), "+f"(c[3])
        : "r"(a[0]), "r"(a[1]), "r"(a[2]), "r"(a[3]), "r"(b[0]), "r"(b[1]));
}

__device__ __forceinline__ void bf16split(float v, bf16& hi, bf16& lo) {
    hi = __float2bfloat16(v);
    lo = __float2bfloat16(v - __bfloat162float(hi));
}

// ---------------------------------------------------------------------------
// weight split: whi/wlo[l*256+co][tap*256+ci] from w[(l,co,ci,tap)]
// ---------------------------------------------------------------------------
__global__ void wsplit_kernel(const float* __restrict__ w,
                              bf16* __restrict__ whi, bf16* __restrict__ wlo)
{
    int i = blockIdx.x * 256 + threadIdx.x;
    if (i >= WBUF) return;
    int row = i / 768;
    int rem = i - row * 768;
    int tap = rem >> 8, ci = rem & 255;
    float v = w[((size_t)row * 256 + ci) * 3 + tap];
    bf16 h, l; bf16split(v, h, l);
    whi[i] = h; wlo[i] = l;
}

// ---------------------------------------------------------------------------
// Projection GEMM (FFMA2, R8 structure); epilogue -> [p][t][c] bf16 hi/lo
// ---------------------------------------------------------------------------
__device__ __forceinline__ void pj_loadA(const float* __restrict__ w, int c0,
                                         int tid, int k0, float pA[8])
{
#pragma unroll
    for (int i = 0; i < 8; i++) {
        int idx = tid + i * 256;
        pA[i] = w[(size_t)(c0 + (idx >> 5)) * MOTIF_C + k0 + (idx & 31)];
    }
}
__device__ __forceinline__ void pj_loadB(const float* __restrict__ x, int pos0,
                                         int tid, int k0, float4 pB[8])
{
#pragma unroll
    for (int i = 0; i < 8; i++) {
        int idx = tid + i * 256;
        pB[i] = *(const float4*)(x + (size_t)(pos0 + (idx >> 3)) * MOTIF_C + k0 + (idx & 7) * 4);
    }
}

__global__ __launch_bounds__(256) void proj_kernel(
    const float* __restrict__ x, const float* __restrict__ w,
    const float* __restrict__ bias,
    bf16* __restrict__ hi_out, bf16* __restrict__ lo_out)
{
    __shared__ float As[32][68];
    __shared__ float Bs[32][256];
    const int tid = threadIdx.x;
    const int tx = tid & 31, ty = tid >> 5;
    const int pos0 = blockIdx.x * 256;
    const int c0 = blockIdx.y * 64;

    ull_t acc[8][4];
#pragma unroll
    for (int i = 0; i < 8; i++)
#pragma unroll
        for (int j = 0; j < 4; j++) acc[i][j] = 0ull;

    float pA[8];
    float4 pB[8];
    pj_loadA(w, c0, tid, 0, pA);
    pj_loadB(x, pos0, tid, 0, pB);

#pragma unroll 1
    for (int k0 = 0; k0 < MOTIF_C; k0 += 32) {
        __syncthreads();
#pragma unroll
        for (int i = 0; i < 8; i++) {
            int idx = tid + i * 256;
            As[idx & 31][idx >> 5] = pA[i];
        }
#pragma unroll
        for (int i = 0; i < 8; i++) {
            int idx = tid + i * 256;
            int f4 = idx & 7, pl = idx >> 3;
            Bs[f4 * 4 + 0][pl] = pB[i].x;
            Bs[f4 * 4 + 1][pl] = pB[i].y;
            Bs[f4 * 4 + 2][pl] = pB[i].z;
            Bs[f4 * 4 + 3][pl] = pB[i].w;
        }
        __syncthreads();
        if (k0 + 32 < MOTIF_C) {
            pj_loadA(w, c0, tid, k0 + 32, pA);
            pj_loadB(x, pos0, tid, k0 + 32, pB);
        }
#pragma unroll
        for (int kk = 0; kk < 32; kk++) {
            float4 a0 = *(const float4*)&As[kk][ty * 4];
            float4 a1 = *(const float4*)&As[kk][32 + ty * 4];
            ull_t av[8];
            av[0] = pack2(a0.x, a0.x); av[1] = pack2(a0.y, a0.y);
            av[2] = pack2(a0.z, a0.z); av[3] = pack2(a0.w, a0.w);
            av[4] = pack2(a1.x, a1.x); av[5] = pack2(a1.y, a1.y);
            av[6] = pack2(a1.z, a1.z); av[7] = pack2(a1.w, a1.w);
            ulonglong2 b0 = *(const ulonglong2*)&Bs[kk][tx * 4];
            ulonglong2 b1 = *(const ulonglong2*)&Bs[kk][128 + tx * 4];
            ull_t bv[4] = {b0.x, b0.y, b1.x, b1.y};
#pragma unroll
            for (int i = 0; i < 8; i++)
#pragma unroll
                for (int j = 0; j < 4; j++)
                    ffma2(acc[i][j], av[i], bv[j]);
        }
    }

#pragma unroll
    for (int ii = 0; ii < 8; ii++) {
        int c = c0 + ((ii < 4) ? (ty * 4 + ii) : (32 + ty * 4 + ii - 4));
        float bvv = bias[c];
#pragma unroll
        for (int g = 0; g < 2; g++) {
            float2 u0 = unpack2(acc[ii][g * 2 + 0]);
            float2 u1 = unpack2(acc[ii][g * 2 + 1]);
            float v[4] = {u0.x, u0.y, u1.x, u1.y};
#pragma unroll
            for (int e = 0; e < 4; e++) {
                int pos = pos0 + g * 128 + tx * 4 + e;
                int pb = pos / 1000;
                int tb = pos - pb * 1000;
                float vv = v[e] + bvv;
                bf16 h, l; bf16split(vv, h, l);
                size_t o = (size_t)pb * POFF + (size_t)tb * 256 + c;
                hi_out[o] = h;
                lo_out[o] = l;
            }
        }
    }
}

// ---------------------------------------------------------------------------
// Dilated conv via mma.sync bf16. CTA: 128co x 128t, K=768 (24 chunks of 32).
// smem tiles [128 rows][32 k] bf16, row stride 80B (conflict-free frags).
// ---------------------------------------------------------------------------
#define TILE_B 10240                  // 128 * 80
#define STG_B  (4 * TILE_B)           // Ahi, Alo, Bhi, Blo
#define DYN_SMEM (2 * STG_B)          // 81920

__global__ __launch_bounds__(256) void dilmma_kernel(
    const bf16* __restrict__ hi_in, const bf16* __restrict__ lo_in,
    const bf16* __restrict__ whi, const bf16* __restrict__ wlo,
    const float* __restrict__ bias,
    bf16* __restrict__ hi_out, bf16* __restrict__ lo_out,
    int dil, int len_out)
{
    extern __shared__ char smc[];
    const int tid = threadIdx.x;
    const int lane = tid & 31, wid = tid >> 5;
    const int warpM = wid >> 2, warpN = wid & 3;
    const int r = lane >> 2, q = lane & 3;
    const int t0 = blockIdx.x * 128;
    const int c0 = blockIdx.y * 128;
    const int p  = blockIdx.z;
    const bf16* __restrict__ hib = hi_in + (size_t)p * POFF;
    const bf16* __restrict__ lob = lo_in + (size_t)p * POFF;

    float acc[4][4][4];
#pragma unroll
    for (int a = 0; a < 4; a++)
#pragma unroll
        for (int b = 0; b < 4; b++)
#pragma unroll
            for (int e = 0; e < 4; e++) acc[a][b][e] = 0.f;

    // --- cp.async fill of one 4-tile stage for chunk ch ---
    auto issue = [&](int ch, char* stg) {
        int tap = ch >> 3, ci0 = (ch & 7) << 5;
        int kc = tap * 256 + ci0;
        unsigned sb = smem_u32(stg);
        int brow0 = t0 + tap * dil;
#pragma unroll
        for (int i = 0; i < 8; i++) {
            int idx = tid + i * 256;
            int tile = i >> 1;
            int row = (idx >> 2) & 127;
            int seg = idx & 3;
            unsigned dst = sb + tile * TILE_B + row * 80 + seg * 16;
            const bf16* src;
            if (tile == 0)      src = whi + (size_t)(c0 + row) * 768 + kc + seg * 8;
            else if (tile == 1) src = wlo + (size_t)(c0 + row) * 768 + kc + seg * 8;
            else if (tile == 2) src = hib + (size_t)(brow0 + row) * 256 + ci0 + seg * 8;
            else                src = lob + (size_t)(brow0 + row) * 256 + ci0 + seg * 8;
            CP16(dst, src);
        }
        asm volatile("cp.async.commit_group;" ::: "memory");
    };

    issue(0, smc);

#pragma unroll 1
    for (int ch = 0; ch < 24; ch++) {
        char* stg = smc + (ch & 1) * STG_B;
        asm volatile("cp.async.wait_group 0;" ::: "memory");
        __syncthreads();
        if (ch + 1 < 24)
            issue(ch + 1, smc + ((ch + 1) & 1) * STG_B);

        const char* A0 = stg;
        const char* A1 = stg + TILE_B;
        const char* B0 = stg + 2 * TILE_B;
        const char* B1 = stg + 3 * TILE_B;
#pragma unroll
        for (int kg = 0; kg < 2; kg++) {
            const int kb = kg * 32 + q * 4;
            unsigned bhi[4][2], blo[4][2];
#pragma unroll
            for (int nt = 0; nt < 4; nt++) {
                int trow = warpN * 32 + nt * 8 + r;
                const char* p0 = B0 + trow * 80 + kb;
                const char* p1 = B1 + trow * 80 + kb;
                bhi[nt][0] = *(const unsigned*)p0;
                bhi[nt][1] = *(const unsigned*)(p0 + 16);
                blo[nt][0] = *(const unsigned*)p1;
                blo[nt][1] = *(const unsigned*)(p1 + 16);
            }
#pragma unroll
            for (int mt = 0; mt < 4; mt++) {
                int mrow = warpM * 64 + mt * 16 + r;
                const char* pa = A0 + mrow * 80 + kb;
                unsigned ahi[4] = {
                    *(const unsigned*)pa, *(const unsigned*)(pa + 640),
                    *(const unsigned*)(pa + 16), *(const unsigned*)(pa + 656)};
#pragma unroll
                for (int nt = 0; nt < 4; nt++)
                    mma16816(acc[mt][nt], ahi, bhi[nt]);
#pragma unroll
                for (int nt = 0; nt < 4; nt++)
                    mma16816(acc[mt][nt], ahi, blo[nt]);
                const char* pl = A1 + mrow * 80 + kb;
                unsigned alo[4] = {
                    *(const unsigned*)pl, *(const unsigned*)(pl + 640),
                    *(const unsigned*)(pl + 16), *(const unsigned*)(pl + 656)};
#pragma unroll
                for (int nt = 0; nt < 4; nt++)
                    mma16816(acc[mt][nt], alo, bhi[nt]);
            }
        }
    }

    // --- epilogue: bias + relu + residual, bf16 split store to [t][c] ---
    bf16* __restrict__ ho = hi_out + (size_t)p * POFF;
    bf16* __restrict__ lo_o = lo_out + (size_t)p * POFF;
#pragma unroll
    for (int mt = 0; mt < 4; mt++) {
        int coA = c0 + warpM * 64 + mt * 16 + r;
        float bvA = bias[coA], bvB = bias[coA + 8];
#pragma unroll
        for (int nt = 0; nt < 4; nt++) {
            int tt = t0 + warpN * 32 + nt * 8 + q * 2;
#pragma unroll
            for (int e = 0; e < 4; e++) {
                int co = coA + ((e >= 2) ? 8 : 0);
                float bv = (e >= 2) ? bvB : bvA;
                int t = tt + (e & 1);
                if (t < len_out) {
                    size_t ri = (size_t)(t + dil) * 256 + co;
                    float v = fmaxf(acc[mt][nt][e] + bv, 0.f)
                            + __bfloat162float(hib[ri]) + __bfloat162float(lob[ri]);
                    bf16 h, l; bf16split(v, h, l);
                    size_t o = (size_t)t * 256 + co;
                    ho[o] = h; lo_o[o] = l;
                }
            }
        }
    }
}

// ---------------------------------------------------------------------------
// Heads ([p][t][c] bf16 hi/lo)
// ---------------------------------------------------------------------------
__global__ __launch_bounds__(256) void atpm_kernel(
    const bf16* __restrict__ hi, const bf16* __restrict__ lo,
    const float* __restrict__ wa, const float* __restrict__ ba,
    float* __restrict__ out)
{
    __shared__ float red[256];
    const int c = threadIdx.x;
    const int p = blockIdx.x;
    const bf16* hb = hi + (size_t)p * POFF;
    const bf16* lb = lo + (size_t)p * POFF;
    float s = 0.f;
#pragma unroll 1
    for (int t = 0; t < 492; t++)
        s += __bfloat162float(hb[t * 256 + c]) + __bfloat162float(lb[t * 256 + c]);
    red[c] = (s * (1.0f / 492.0f)) * wa[c];
    __syncthreads();
    for (int off = 128; off > 0; off >>= 1) {
        if (c < off) red[c] += red[c + off];
        __syncthreads();
    }
    if (c == 0) out[p] = softplusf(red[0] + ba[0]);
}

__global__ __launch_bounds__(256) void profile_kernel(
    const bf16* __restrict__ hi, const bf16* __restrict__ lo,
    const float* __restrict__ wp, const float* __restrict__ bp,
    float* __restrict__ out)
{
    __shared__ float red[256];
    const int c = threadIdx.x;
    const int t = blockIdx.x;
    const int p = blockIdx.y;
    const bf16* hb = hi + (size_t)p * POFF;
    const bf16* lb = lo + (size_t)p * POFF;
    float s = 0.f;
#pragma unroll 1
    for (int j = 0; j < 75; j++) {
        int idx = (t + j) * 256 + c;
        s = fmaf(__bfloat162float(hb[idx]) + __bfloat162float(lb[idx]),
                 wp[c * 75 + j], s);
    }
    red[c] = s;
    __syncthreads();
    for (int off = 128; off > 0; off >>= 1) {
        if (c < off) red[c] += red[c + off];
        __syncthreads();
    }
    if (c == 0) out[128 + p * 418 + t] = softplusf(red[0] + bp[0]);
}

// ---------------------------------------------------------------------------
extern "C" void kernel_launch(void* const* d_in, const int* in_sizes, int n_in,
                              void* d_out, int out_size)
{
    (void)out_size;
    int pbase = 4;
    if (n_in == 11) pbase = 3;
    else if (n_in == 12 && in_sizes[3] != 1) pbase = 3;

    const float* x      = (const float*)d_in[0];
    const float* w_proj = (const float*)d_in[pbase + 0];
    const float* b_proj = (const float*)d_in[pbase + 1];
    const float* w_dil  = (const float*)d_in[pbase + 2];
    const float* b_dil  = (const float*)d_in[pbase + 3];
    const float* w_prof = (const float*)d_in[pbase + 4];
    const float* b_prof = (const float*)d_in[pbase + 5];
    const float* w_atpm = (const float*)d_in[pbase + 6];
    const float* b_atpm = (const float*)d_in[pbase + 7];
    float* out = (float*)d_out;

    bf16 *hiA, *loA, *hiB, *loB, *whi, *wlo;
    cudaGetSymbolAddress((void**)&hiA, g_hiA);
    cudaGetSymbolAddress((void**)&loA, g_loA);
    cudaGetSymbolAddress((void**)&hiB, g_hiB);
    cudaGetSymbolAddress((void**)&loB, g_loB);
    cudaGetSymbolAddress((void**)&whi, g_whi);
    cudaGetSymbolAddress((void**)&wlo, g_wlo);

    cudaFuncSetAttribute(dilmma_kernel,
                         cudaFuncAttributeMaxDynamicSharedMemorySize, DYN_SMEM);

    wsplit_kernel<<<(WBUF + 255) / 256, 256>>>(w_dil, whi, wlo);
    proj_kernel<<<dim3(500, 4), 256>>>(x, w_proj, b_proj, hiA, loA);

    static const int lens[8] = {1000, 996, 988, 972, 940, 876, 748, 492};
    bf16 *ch = hiA, *cl = loA, *nh = hiB, *nl = loB;
    for (int l = 0; l < 7; l++) {
        int dil = 2 << l;
        int lo_len = lens[l + 1];
        dim3 grid((lo_len + 127) / 128, 2, NPEAK);
        dilmma_kernel<<<grid, 256, DYN_SMEM>>>(
            ch, cl, whi + (size_t)l * 196608, wlo + (size_t)l * 196608,
            b_dil + l * 256, nh, nl, dil, lo_len);
        bf16* t1 = ch; ch = nh; nh = t1;
        bf16* t2 = cl; cl = nl; nl = t2;
    }

    atpm_kernel<<<NPEAK, 256>>>(ch, cl, w_atpm, b_atpm, out);
    profile_kernel<<<dim3(418, NPEAK), 256>>>(ch, cl, w_prof, b_prof, out);
}

// round 15
// speedup vs baseline: 1.8785x; 1.3545x over previous
#include <cuda_runtime.h>
#include <cuda_bf16.h>
#include <cstdint>
#include <cstddef>

// ---------------------------------------------------------------------------
// ConvPool: 1x1 proj GEMM (FFMA2) -> 7x dilated conv tower on mma.sync HMMA
// (3-term bf16 split, fp32 accum) -> fp32 heads.
// R14 = R13 + OOB fix: profile_kernel clamps its read index (t up to 447
// was reading past g_fin with the compact FSTR=512 stride).
// ---------------------------------------------------------------------------

#define NPEAK 128
#define HIDC  256
#define MOTIF_C 640
#define POFF  (1000 * 256)                 // per-peak elems in [t][c] layout
#define HBUF  (NPEAK * POFF + 131072)
#define WBUF  (7 * 256 * 768)
#define FSTR  512                           // fin row stride (fp32 [c][t])

typedef unsigned long long ull_t;
typedef __nv_bfloat16 bf16;

__device__ bf16 g_hiA[HBUF];
__device__ bf16 g_loA[HBUF];
__device__ bf16 g_hiB[HBUF];
__device__ bf16 g_loB[HBUF];
__device__ bf16 g_whi[WBUF];
__device__ bf16 g_wlo[WBUF];
__device__ float g_fin[NPEAK * HIDC * FSTR];

// ---- helpers --------------------------------------------------------------
__device__ __forceinline__ float softplusf(float x) {
    return fmaxf(x, 0.0f) + log1pf(expf(-fabsf(x)));
}
__device__ __forceinline__ ull_t pack2(float x, float y) {
    ull_t r; asm("mov.b64 %0, {%1, %2};" : "=l"(r) : "f"(x), "f"(y)); return r;
}
__device__ __forceinline__ float2 unpack2(ull_t v) {
    float2 r; asm("mov.b64 {%0, %1}, %2;" : "=f"(r.x), "=f"(r.y) : "l"(v)); return r;
}
__device__ __forceinline__ void ffma2(ull_t& d, ull_t a, ull_t b) {
    asm("fma.rn.f32x2 %0, %1, %2, %0;" : "+l"(d) : "l"(a), "l"(b));
}
__device__ __forceinline__ unsigned smem_u32(const void* p) {
    unsigned r;
    asm("{ .reg .u64 t; cvta.to.shared.u64 t, %1; cvt.u32.u64 %0, t; }"
        : "=r"(r) : "l"(p));
    return r;
}
#define CP16(dst, src) \
    asm volatile("cp.async.ca.shared.global [%0], [%1], 16;" \
                 :: "r"(dst), "l"(src) : "memory")

__device__ __forceinline__ void mma16816(float c[4], const unsigned a[4],
                                         const unsigned b[2]) {
    asm volatile(
        "mma.sync.aligned.m16n8k16.row.col.f32.bf16.bf16.f32 "
        "{%0,%1,%2,%3}, {%4,%5,%6,%7}, {%8,%9}, {%0,%1,%2,%3};"
        : "+f"(c[0]), "+f"(c[1]), "+f"(c[2]), "+f"(c[3])
        : "r"(a[0]), "r"(a[1]), "r"(a[2]), "r"(a[3]), "r"(b[0]), "r"(b[1]));
}
__device__ __forceinline__ void ldsm_x4(unsigned r[4], unsigned addr) {
    asm volatile("ldmatrix.sync.aligned.m8n8.x4.shared.b16 {%0,%1,%2,%3}, [%4];"
        : "=r"(r[0]), "=r"(r[1]), "=r"(r[2]), "=r"(r[3]) : "r"(addr));
}
__device__ __forceinline__ void bf16split(float v, bf16& hi, bf16& lo) {
    hi = __float2bfloat16(v);
    lo = __float2bfloat16(v - __bfloat162float(hi));
}

// ---------------------------------------------------------------------------
// weight split: whi/wlo[l*256+co][tap*256+ci] from w[(l,co,ci,tap)]
// ---------------------------------------------------------------------------
__global__ void wsplit_kernel(const float* __restrict__ w,
                              bf16* __restrict__ whi, bf16* __restrict__ wlo)
{
    int i = blockIdx.x * 256 + threadIdx.x;
    if (i >= WBUF) return;
    int row = i / 768;
    int rem = i - row * 768;
    int tap = rem >> 8, ci = rem & 255;
    float v = w[((size_t)row * 256 + ci) * 3 + tap];
    bf16 h, l; bf16split(v, h, l);
    whi[i] = h; wlo[i] = l;
}

// ---------------------------------------------------------------------------
// Projection GEMM (FFMA2); epilogue -> [p][t][c] bf16 hi/lo
// ---------------------------------------------------------------------------
__device__ __forceinline__ void pj_loadA(const float* __restrict__ w, int c0,
                                         int tid, int k0, float pA[8])
{
#pragma unroll
    for (int i = 0; i < 8; i++) {
        int idx = tid + i * 256;
        pA[i] = w[(size_t)(c0 + (idx >> 5)) * MOTIF_C + k0 + (idx & 31)];
    }
}
__device__ __forceinline__ void pj_loadB(const float* __restrict__ x, int pos0,
                                         int tid, int k0, float4 pB[8])
{
#pragma unroll
    for (int i = 0; i < 8; i++) {
        int idx = tid + i * 256;
        pB[i] = *(const float4*)(x + (size_t)(pos0 + (idx >> 3)) * MOTIF_C + k0 + (idx & 7) * 4);
    }
}

__global__ __launch_bounds__(256) void proj_kernel(
    const float* __restrict__ x, const float* __restrict__ w,
    const float* __restrict__ bias,
    bf16* __restrict__ hi_out, bf16* __restrict__ lo_out)
{
    __shared__ float As[32][68];
    __shared__ float Bs[32][256];
    const int tid = threadIdx.x;
    const int tx = tid & 31, ty = tid >> 5;
    const int pos0 = blockIdx.x * 256;
    const int c0 = blockIdx.y * 64;

    ull_t acc[8][4];
#pragma unroll
    for (int i = 0; i < 8; i++)
#pragma unroll
        for (int j = 0; j < 4; j++) acc[i][j] = 0ull;

    float pA[8];
    float4 pB[8];
    pj_loadA(w, c0, tid, 0, pA);
    pj_loadB(x, pos0, tid, 0, pB);

#pragma unroll 1
    for (int k0 = 0; k0 < MOTIF_C; k0 += 32) {
        __syncthreads();
#pragma unroll
        for (int i = 0; i < 8; i++) {
            int idx = tid + i * 256;
            As[idx & 31][idx >> 5] = pA[i];
        }
#pragma unroll
        for (int i = 0; i < 8; i++) {
            int idx = tid + i * 256;
            int f4 = idx & 7, pl = idx >> 3;
            Bs[f4 * 4 + 0][pl] = pB[i].x;
            Bs[f4 * 4 + 1][pl] = pB[i].y;
            Bs[f4 * 4 + 2][pl] = pB[i].z;
            Bs[f4 * 4 + 3][pl] = pB[i].w;
        }
        __syncthreads();
        if (k0 + 32 < MOTIF_C) {
            pj_loadA(w, c0, tid, k0 + 32, pA);
            pj_loadB(x, pos0, tid, k0 + 32, pB);
        }
#pragma unroll
        for (int kk = 0; kk < 32; kk++) {
            float4 a0 = *(const float4*)&As[kk][ty * 4];
            float4 a1 = *(const float4*)&As[kk][32 + ty * 4];
            ull_t av[8];
            av[0] = pack2(a0.x, a0.x); av[1] = pack2(a0.y, a0.y);
            av[2] = pack2(a0.z, a0.z); av[3] = pack2(a0.w, a0.w);
            av[4] = pack2(a1.x, a1.x); av[5] = pack2(a1.y, a1.y);
            av[6] = pack2(a1.z, a1.z); av[7] = pack2(a1.w, a1.w);
            ulonglong2 b0 = *(const ulonglong2*)&Bs[kk][tx * 4];
            ulonglong2 b1 = *(const ulonglong2*)&Bs[kk][128 + tx * 4];
            ull_t bv[4] = {b0.x, b0.y, b1.x, b1.y};
#pragma unroll
            for (int i = 0; i < 8; i++)
#pragma unroll
                for (int j = 0; j < 4; j++)
                    ffma2(acc[i][j], av[i], bv[j]);
        }
    }

#pragma unroll
    for (int ii = 0; ii < 8; ii++) {
        int c = c0 + ((ii < 4) ? (ty * 4 + ii) : (32 + ty * 4 + ii - 4));
        float bvv = bias[c];
#pragma unroll
        for (int g = 0; g < 2; g++) {
            float2 u0 = unpack2(acc[ii][g * 2 + 0]);
            float2 u1 = unpack2(acc[ii][g * 2 + 1]);
            float v[4] = {u0.x, u0.y, u1.x, u1.y};
#pragma unroll
            for (int e = 0; e < 4; e++) {
                int pos = pos0 + g * 128 + tx * 4 + e;
                int pb = pos / 1000;
                int tb = pos - pb * 1000;
                float vv = v[e] + bvv;
                bf16 h, l; bf16split(vv, h, l);
                size_t o = (size_t)pb * POFF + (size_t)tb * 256 + c;
                hi_out[o] = h;
                lo_out[o] = l;
            }
        }
    }
}

// ---------------------------------------------------------------------------
// Dilated conv via mma.sync bf16 + ldmatrix. CTA: 128co x 128t, K=768.
// smem tiles [128 rows][32 k] bf16, row stride 80B.
// ---------------------------------------------------------------------------
#define TILE_B 10240                  // 128 * 80
#define STG_B  (4 * TILE_B)           // Ahi, Alo, Bhi, Blo
#define DYN_SMEM (2 * STG_B)          // 81920

__global__ __launch_bounds__(256, 2) void dilmma_kernel(
    const bf16* __restrict__ hi_in, const bf16* __restrict__ lo_in,
    const bf16* __restrict__ whi, const bf16* __restrict__ wlo,
    const float* __restrict__ bias,
    bf16* __restrict__ hi_out, bf16* __restrict__ lo_out,
    float* __restrict__ fin,          // fp32 [p][c][t] stride FSTR (last layer)
    int dil, int len_out)
{
    extern __shared__ char smc[];
    const int tid = threadIdx.x;
    const int lane = tid & 31, wid = tid >> 5;
    const int warpM = wid >> 2, warpN = wid & 3;
    const int r = lane >> 2, q = lane & 3;
    const int t0 = blockIdx.x * 128;
    const int c0 = blockIdx.y * 128;
    const int p  = blockIdx.z;
    const bf16* __restrict__ hib = hi_in + (size_t)p * POFF;
    const bf16* __restrict__ lob = lo_in + (size_t)p * POFF;

    // ldmatrix per-lane address offsets (bytes)
    const unsigned aOff = (unsigned)((lane & 15) * 80 + (lane >> 4) * 16);
    const unsigned bOff = (unsigned)(((lane & 7) + ((lane >> 4) << 3)) * 80 +
                                     (((lane >> 3) & 1) << 4));

    float acc[4][4][4];
#pragma unroll
    for (int a = 0; a < 4; a++)
#pragma unroll
        for (int b = 0; b < 4; b++)
#pragma unroll
            for (int e = 0; e < 4; e++) acc[a][b][e] = 0.f;

    auto issue = [&](int ch, char* stg) {
        int tap = ch >> 3, ci0 = (ch & 7) << 5;
        int kc = tap * 256 + ci0;
        unsigned sb = smem_u32(stg);
        int brow0 = t0 + tap * dil;
#pragma unroll
        for (int i = 0; i < 8; i++) {
            int idx = tid + i * 256;
            int tile = i >> 1;
            int row = (idx >> 2) & 127;
            int seg = idx & 3;
            unsigned dst = sb + tile * TILE_B + row * 80 + seg * 16;
            const bf16* src;
            if (tile == 0)      src = whi + (size_t)(c0 + row) * 768 + kc + seg * 8;
            else if (tile == 1) src = wlo + (size_t)(c0 + row) * 768 + kc + seg * 8;
            else if (tile == 2) src = hib + (size_t)(brow0 + row) * 256 + ci0 + seg * 8;
            else                src = lob + (size_t)(brow0 + row) * 256 + ci0 + seg * 8;
            CP16(dst, src);
        }
        asm volatile("cp.async.commit_group;" ::: "memory");
    };

    issue(0, smc);

#pragma unroll 1
    for (int ch = 0; ch < 24; ch++) {
        char* stg = smc + (ch & 1) * STG_B;
        asm volatile("cp.async.wait_group 0;" ::: "memory");
        __syncthreads();
        if (ch + 1 < 24)
            issue(ch + 1, smc + ((ch + 1) & 1) * STG_B);

        const unsigned sA = smem_u32(stg);
        const unsigned sB = sA + 2 * TILE_B;
#pragma unroll
        for (int kg = 0; kg < 2; kg++) {
            const unsigned kby = kg * 32;
            unsigned bhi[8], blo[8];
            {
                unsigned bb = sB + (unsigned)(warpN * 32) * 80 + kby + bOff;
                ldsm_x4(bhi,     bb);
                ldsm_x4(bhi + 4, bb + 16 * 80);
                ldsm_x4(blo,     bb + TILE_B);
                ldsm_x4(blo + 4, bb + TILE_B + 16 * 80);
            }
#pragma unroll
            for (int mtp = 0; mtp < 2; mtp++) {
                unsigned ahi[8], alo[8];
                unsigned ab = sA + (unsigned)(warpM * 64 + mtp * 32) * 80 + kby + aOff;
                ldsm_x4(ahi,     ab);
                ldsm_x4(ahi + 4, ab + 16 * 80);
                ldsm_x4(alo,     ab + TILE_B);
                ldsm_x4(alo + 4, ab + TILE_B + 16 * 80);
                // term hh (acc reuse distance 8)
#pragma unroll
                for (int m2 = 0; m2 < 2; m2++)
#pragma unroll
                    for (int nt = 0; nt < 4; nt++)
                        mma16816(acc[mtp * 2 + m2][nt], ahi + m2 * 4, bhi + nt * 2);
                // term hl
#pragma unroll
                for (int m2 = 0; m2 < 2; m2++)
#pragma unroll
                    for (int nt = 0; nt < 4; nt++)
                        mma16816(acc[mtp * 2 + m2][nt], ahi + m2 * 4, blo + nt * 2);
                // term lh
#pragma unroll
                for (int m2 = 0; m2 < 2; m2++)
#pragma unroll
                    for (int nt = 0; nt < 4; nt++)
                        mma16816(acc[mtp * 2 + m2][nt], alo + m2 * 4, bhi + nt * 2);
            }
        }
    }

    // --- epilogue: bias + relu + residual; bf16 split store + optional fp32 ---
    bf16* __restrict__ ho = hi_out + (size_t)p * POFF;
    bf16* __restrict__ lo_o = lo_out + (size_t)p * POFF;
    float* __restrict__ fo = fin ? fin + (size_t)p * (HIDC * FSTR) : (float*)0;
#pragma unroll
    for (int mt = 0; mt < 4; mt++) {
        int coA = c0 + warpM * 64 + mt * 16 + r;
        float bvA = bias[coA], bvB = bias[coA + 8];
#pragma unroll
        for (int nt = 0; nt < 4; nt++) {
            int tt = t0 + warpN * 32 + nt * 8 + q * 2;
#pragma unroll
            for (int e = 0; e < 4; e++) {
                int co = coA + ((e >= 2) ? 8 : 0);
                float bv = (e >= 2) ? bvB : bvA;
                int t = tt + (e & 1);
                if (t < len_out) {
                    size_t ri = (size_t)(t + dil) * 256 + co;
                    float v = fmaxf(acc[mt][nt][e] + bv, 0.f)
                            + __bfloat162float(hib[ri]) + __bfloat162float(lob[ri]);
                    bf16 h, l; bf16split(v, h, l);
                    size_t o = (size_t)t * 256 + co;
                    ho[o] = h; lo_o[o] = l;
                    if (fo) fo[(size_t)co * FSTR + t] = v;
                }
            }
        }
    }
}

// ---------------------------------------------------------------------------
// Heads: fp32 [p][c][t] stride FSTR (R8-style tiled)
// ---------------------------------------------------------------------------
__global__ __launch_bounds__(256) void atpm_kernel(
    const float* __restrict__ fin, const float* __restrict__ wa,
    const float* __restrict__ ba, float* __restrict__ out)
{
    __shared__ float red[256];
    const int tid = threadIdx.x;
    const int p = blockIdx.x;
    const float* __restrict__ hr = fin + (size_t)p * (HIDC * FSTR) + (size_t)tid * FSTR;
    float s = 0.f;
#pragma unroll 1
    for (int t4 = 0; t4 < 492; t4 += 4) {
        float4 v = *(const float4*)(hr + t4);
        s += (v.x + v.y) + (v.z + v.w);
    }
    red[tid] = (s * (1.0f / 492.0f)) * wa[tid];
    __syncthreads();
    for (int off = 128; off > 0; off >>= 1) {
        if (tid < off) red[tid] += red[tid + off];
        __syncthreads();
    }
    if (tid == 0) out[p] = softplusf(red[0] + ba[0]);
}

__global__ __launch_bounds__(256) void profile_kernel(
    const float* __restrict__ fin, const float* __restrict__ wp,
    const float* __restrict__ bp, float* __restrict__ out)
{
    __shared__ float ws[64 * 75];
    __shared__ float red[256];
    const int tid = threadIdx.x;
    const int tt = tid & 63, g = tid >> 6;
    const int p = blockIdx.y;
    const int t = blockIdx.x * 64 + tt;
    // clamp the READ index: threads with t >= 418 are discarded at the write,
    // but their reads must stay in-bounds (t up to 447; 447+74 > FSTR).
    const int tr = (t < 418) ? t : 417;
    const float* __restrict__ hp = fin + (size_t)p * (HIDC * FSTR);

    float acc = 0.f;
#pragma unroll 1
    for (int cb = 0; cb < HIDC; cb += 64) {
        __syncthreads();
        for (int idx = tid; idx < 64 * 75; idx += 256) ws[idx] = wp[cb * 75 + idx];
        __syncthreads();
#pragma unroll 1
        for (int cc = 0; cc < 16; cc++) {
            int c = cb + g * 16 + cc;
            const float* hr = hp + (size_t)c * FSTR + tr;
            const float* wr = ws + (g * 16 + cc) * 75;
            float s = 0.f;
#pragma unroll
            for (int j = 0; j < 75; j++) s = fmaf(hr[j], wr[j], s);
            acc += s;
        }
    }
    red[tid] = acc;
    __syncthreads();
    if (g == 0 && t < 418) {
        float tot = red[tt] + red[tt + 64] + red[tt + 128] + red[tt + 192] + bp[0];
        out[128 + p * 418 + t] = softplusf(tot);
    }
}

// ---------------------------------------------------------------------------
extern "C" void kernel_launch(void* const* d_in, const int* in_sizes, int n_in,
                              void* d_out, int out_size)
{
    (void)out_size;
    int pbase = 4;
    if (n_in == 11) pbase = 3;
    else if (n_in == 12 && in_sizes[3] != 1) pbase = 3;

    const float* x      = (const float*)d_in[0];
    const float* w_proj = (const float*)d_in[pbase + 0];
    const float* b_proj = (const float*)d_in[pbase + 1];
    const float* w_dil  = (const float*)d_in[pbase + 2];
    const float* b_dil  = (const float*)d_in[pbase + 3];
    const float* w_prof = (const float*)d_in[pbase + 4];
    const float* b_prof = (const float*)d_in[pbase + 5];
    const float* w_atpm = (const float*)d_in[pbase + 6];
    const float* b_atpm = (const float*)d_in[pbase + 7];
    float* out = (float*)d_out;

    bf16 *hiA, *loA, *hiB, *loB, *whi, *wlo;
    float* fin;
    cudaGetSymbolAddress((void**)&hiA, g_hiA);
    cudaGetSymbolAddress((void**)&loA, g_loA);
    cudaGetSymbolAddress((void**)&hiB, g_hiB);
    cudaGetSymbolAddress((void**)&loB, g_loB);
    cudaGetSymbolAddress((void**)&whi, g_whi);
    cudaGetSymbolAddress((void**)&wlo, g_wlo);
    cudaGetSymbolAddress((void**)&fin, g_fin);

    cudaFuncSetAttribute(dilmma_kernel,
                         cudaFuncAttributeMaxDynamicSharedMemorySize, DYN_SMEM);

    wsplit_kernel<<<(WBUF + 255) / 256, 256>>>(w_dil, whi, wlo);
    proj_kernel<<<dim3(500, 4), 256>>>(x, w_proj, b_proj, hiA, loA);

    static const int lens[8] = {1000, 996, 988, 972, 940, 876, 748, 492};
    bf16 *ch = hiA, *cl = loA, *nh = hiB, *nl = loB;
    for (int l = 0; l < 7; l++) {
        int dil = 2 << l;
        int lo_len = lens[l + 1];
        dim3 grid((lo_len + 127) / 128, 2, NPEAK);
        dilmma_kernel<<<grid, 256, DYN_SMEM>>>(
            ch, cl, whi + (size_t)l * 196608, wlo + (size_t)l * 196608,
            b_dil + l * 256, nh, nl, (l == 6) ? fin : (float*)0, dil, lo_len);
        bf16* t1 = ch; ch = nh; nh = t1;
        bf16* t2 = cl; cl = nl; nl = t2;
    }

    atpm_kernel<<<NPEAK, 256>>>(fin, w_atpm, b_atpm, out);
    profile_kernel<<<dim3(7, NPEAK), 256>>>(fin, w_prof, b_prof, out);
}